// round 16
// baseline (speedup 1.0000x reference)
#include <cuda_runtime.h>
#include <cuda_fp16.h>
#include <cstdint>

#define B_BATCH 2
#define SEQ 2048
#define EMBED 1024
#define HEADS 16
#define HDIM 64
#define MROWS (B_BATCH * SEQ)   // 4096

// ---------------- scratch (device globals: allocation-free) ----------------
__device__ __half g_Ah[(size_t)MROWS * EMBED];                  // fp16-rounded query
__device__ __half g_Qh[(size_t)MROWS * EMBED];
__device__ __half g_Kh[(size_t)MROWS * EMBED];
__device__ __half g_Vh[(size_t)MROWS * EMBED];
__device__ __half g_Oh[(size_t)MROWS * EMBED];
__device__ __half g_Wth[(size_t)4 * EMBED * EMBED];             // transposed weights (fp16)
__device__ float g_qsq[(size_t)B_BATCH * HEADS * SEQ];
__device__ float g_ksq[(size_t)B_BATCH * HEADS * SEQ];

// ======================= helpers =======================
__device__ __forceinline__ uint32_t smem_u32(const void* p) {
    uint32_t a;
    asm("{ .reg .u64 t; cvta.to.shared.u64 t, %1; cvt.u32.u64 %0, t; }" : "=r"(a) : "l"(p));
    return a;
}
__device__ __forceinline__ void cp_async16(uint32_t dst, const void* src) {
    asm volatile("cp.async.cg.shared.global [%0], [%1], 16;" :: "r"(dst), "l"(src));
}
#define CP_COMMIT() asm volatile("cp.async.commit_group;" ::: "memory")
#define CP_WAIT0()  asm volatile("cp.async.wait_group 0;" ::: "memory")
#define CP_WAIT1()  asm volatile("cp.async.wait_group 1;" ::: "memory")

// mma.sync m16n8k16 fp16: D(f32) += A(f16)*B(f16)
__device__ __forceinline__ void mma_f16(float* d, const uint32_t* a, const uint32_t* b) {
    asm volatile(
        "mma.sync.aligned.m16n8k16.row.col.f32.f16.f16.f32 "
        "{%0,%1,%2,%3}, {%4,%5,%6,%7}, {%8,%9}, {%0,%1,%2,%3};"
        : "+f"(d[0]), "+f"(d[1]), "+f"(d[2]), "+f"(d[3])
        : "r"(a[0]), "r"(a[1]), "r"(a[2]), "r"(a[3]), "r"(b[0]), "r"(b[1]));
}
__device__ __forceinline__ void ldmx4(uint32_t* r, uint32_t addr) {
    asm volatile("ldmatrix.sync.aligned.m8n8.x4.shared.b16 {%0,%1,%2,%3}, [%4];"
        : "=r"(r[0]), "=r"(r[1]), "=r"(r[2]), "=r"(r[3]) : "r"(addr));
}
__device__ __forceinline__ void ldmx4t(uint32_t* r, uint32_t addr) {
    asm volatile("ldmatrix.sync.aligned.m8n8.x4.trans.shared.b16 {%0,%1,%2,%3}, [%4];"
        : "=r"(r[0]), "=r"(r[1]), "=r"(r[2]), "=r"(r[3]) : "r"(addr));
}

// ======================= round query to fp16 =======================
__global__ __launch_bounds__(256) void round_query_kernel(const float* __restrict__ in)
{
    size_t i = ((size_t)blockIdx.x * 256 + threadIdx.x) * 8;
    float4 a = *(const float4*)&in[i];
    float4 b = *(const float4*)&in[i + 4];
    __half2 h[4];
    h[0] = __floats2half2_rn(a.x, a.y);
    h[1] = __floats2half2_rn(a.z, a.w);
    h[2] = __floats2half2_rn(b.x, b.y);
    h[3] = __floats2half2_rn(b.z, b.w);
    *(uint4*)&g_Ah[i] = *(uint4*)h;
}

// ======================= transpose weights (+fp16 round) =======================
__global__ __launch_bounds__(256) void transpose_w_kernel(
    const float* __restrict__ wq, const float* __restrict__ wk,
    const float* __restrict__ wv, const float* __restrict__ wo)
{
    __shared__ float t[32][33];
    const int z = blockIdx.z;
    const float* W = (z == 0) ? wq : (z == 1) ? wk : (z == 2) ? wv : wo;
    __half* Out = g_Wth + (size_t)z * EMBED * EMBED;
    const int k0 = blockIdx.x * 32, n0 = blockIdx.y * 32;
    const int tx = threadIdx.x & 31, ty = threadIdx.x >> 5;
#pragma unroll
    for (int i = 0; i < 4; i++)
        t[ty + i * 8][tx] = W[(size_t)(k0 + ty + i * 8) * EMBED + n0 + tx];
    __syncthreads();
#pragma unroll
    for (int i = 0; i < 4; i++)
        Out[(size_t)(n0 + ty + i * 8) * EMBED + k0 + tx] = __float2half_rn(t[tx][ty + i * 8]);
}

// ======================= fp16 mma projection GEMM (128x128, BK=64, 3-stage) =======
// 256 threads, 8 warps (64x32 each). Stage: A[128][72] + B[128][72] halfs = 36864 B.
// HOUT (QKV) launches z<2 also emit per-row head-norms into g_qsq/g_ksq.
#define PROJ_STAGE_B 36864
#define PROJ_SMEM    (3 * PROJ_STAGE_B)   // 110592 bytes

template <bool HOUT>
__global__ __launch_bounds__(256, 2) void proj_h_kernel(
    const __half* __restrict__ A,
    const __half* __restrict__ B0, const __half* __restrict__ B1, const __half* __restrict__ B2,
    const float* __restrict__ bias0, const float* __restrict__ bias1, const float* __restrict__ bias2,
    void* __restrict__ C0v, void* __restrict__ C1v, void* __restrict__ C2v)
{
    extern __shared__ __align__(16) char smb[];
    const int z = blockIdx.z;
    const __half* Bt = (z == 0) ? B0 : (z == 1) ? B1 : B2;
    const float* bias = (z == 0) ? bias0 : (z == 1) ? bias1 : bias2;
    void* Cv = (z == 0) ? C0v : (z == 1) ? C1v : C2v;

    const uint32_t sBase = smem_u32(smb);
    const int tid = threadIdx.x, lane = tid & 31, warp = tid >> 5;
    const int g = lane >> 2, tg = lane & 3;
    const int m0 = blockIdx.y * 128, n0 = blockIdx.x * 128;
    const int mw = (warp >> 2) * 64, nw = (warp & 3) * 32;

    const uint32_t aOff = (mw + (lane & 15)) * 144 + ((lane >> 4) << 4);
    const uint32_t bOff = 18432 +
        (nw + (lane & 7) + ((lane >> 4) << 3)) * 144 + (((lane >> 3) & 1) << 4);

    float acc[4][4][4];
#pragma unroll
    for (int mi = 0; mi < 4; mi++)
#pragma unroll
        for (int ni = 0; ni < 4; ni++)
#pragma unroll
            for (int c = 0; c < 4; c++) acc[mi][ni][c] = 0.f;

    auto issue = [&](int kc) {
        const uint32_t sb = sBase + (kc % 3) * PROJ_STAGE_B;
        const int k0 = kc * 64;
#pragma unroll
        for (int it = 0; it < 4; it++) {
            int idx = tid + it * 256;
            int r = idx >> 3, c = idx & 7;
            cp_async16(sb + r * 144 + c * 16, &A[(size_t)(m0 + r) * EMBED + k0 + c * 8]);
            cp_async16(sb + 18432 + r * 144 + c * 16, &Bt[(size_t)(n0 + r) * EMBED + k0 + c * 8]);
        }
        CP_COMMIT();
    };

    issue(0); issue(1);
    for (int kc = 0; kc < 16; kc++) {
        if (kc == 15) { CP_WAIT0(); } else { CP_WAIT1(); }
        __syncthreads();
        if (kc + 2 < 16) issue(kc + 2);
        const uint32_t sb = sBase + (kc % 3) * PROJ_STAGE_B;
#pragma unroll
        for (int ks = 0; ks < 4; ks++) {
            const uint32_t kb = ks * 32;
            uint32_t af[4][4], bf[4][2];
#pragma unroll
            for (int mi = 0; mi < 4; mi++)
                ldmx4(af[mi], sb + aOff + mi * 2304 + kb);
#pragma unroll
            for (int j = 0; j < 2; j++) {
                uint32_t t[4];
                ldmx4(t, sb + bOff + j * 2304 + kb);
                bf[j * 2][0] = t[0]; bf[j * 2][1] = t[1];
                bf[j * 2 + 1][0] = t[2]; bf[j * 2 + 1][1] = t[3];
            }
#pragma unroll
            for (int mi = 0; mi < 4; mi++)
#pragma unroll
                for (int ni = 0; ni < 4; ni++)
                    mma_f16(acc[mi][ni], af[mi], bf[ni]);
        }
        __syncthreads();
    }

    float rp[8];
#pragma unroll
    for (int i = 0; i < 8; i++) rp[i] = 0.f;

#pragma unroll
    for (int mi = 0; mi < 4; mi++)
#pragma unroll
        for (int ni = 0; ni < 4; ni++) {
            int row = m0 + mw + mi * 16 + g;
            int col = n0 + nw + ni * 8 + tg * 2;
            float b0 = bias[col], b1 = bias[col + 1];
            if (HOUT) {
                __half* C = (__half*)Cv;
                __half2 h0 = __floats2half2_rn(acc[mi][ni][0] + b0, acc[mi][ni][1] + b1);
                __half2 h1 = __floats2half2_rn(acc[mi][ni][2] + b0, acc[mi][ni][3] + b1);
                *(__half2*)&C[(size_t)row * EMBED + col] = h0;
                *(__half2*)&C[(size_t)(row + 8) * EMBED + col] = h1;
                if (z < 2) {
                    float2 f0 = __half22float2(h0);
                    float2 f1 = __half22float2(h1);
                    rp[mi * 2 + 0] += f0.x * f0.x + f0.y * f0.y;
                    rp[mi * 2 + 1] += f1.x * f1.x + f1.y * f1.y;
                }
            } else {
                float* C = (float*)Cv;
                float2 v0 = { acc[mi][ni][0] + b0, acc[mi][ni][1] + b1 };
                float2 v1 = { acc[mi][ni][2] + b0, acc[mi][ni][3] + b1 };
                *(float2*)&C[(size_t)row * EMBED + col] = v0;
                *(float2*)&C[(size_t)(row + 8) * EMBED + col] = v1;
            }
        }

    if (HOUT && z < 2) {
#pragma unroll
        for (int i = 0; i < 8; i++) {
            rp[i] += __shfl_xor_sync(0xffffffffu, rp[i], 1);
            rp[i] += __shfl_xor_sync(0xffffffffu, rp[i], 2);
        }
        float* nsum = (float*)smb;
        __syncthreads();
        if (tg == 0) {
#pragma unroll
            for (int mi = 0; mi < 4; mi++) {
                nsum[(mw + mi * 16 + g) * 4 + (warp & 3)]     = rp[mi * 2 + 0];
                nsum[(mw + mi * 16 + g + 8) * 4 + (warp & 3)] = rp[mi * 2 + 1];
            }
        }
        __syncthreads();
        if (tid < 128) {
            int grow = m0 + tid;
            int bb = grow >> 11, s = grow & (SEQ - 1);
            int head0 = n0 >> 6;
            float v0 = nsum[tid * 4 + 0] + nsum[tid * 4 + 1];
            float v1 = nsum[tid * 4 + 2] + nsum[tid * 4 + 3];
            float* dst = (z == 0) ? g_qsq : g_ksq;
            dst[(size_t)(bb * HEADS + head0) * SEQ + s]     = v0;
            dst[(size_t)(bb * HEADS + head0 + 1) * SEQ + s] = v1;
        }
    }
}

// ======================= fused attention (fp16 mma, q128, trans-V, 2 CTAs/SM) ============
// Per block: one (b,h), one 128-row q-tile; 16 k-tiles of 128. 256 threads, 8 warps.
// Smem (halfs): Qs[128][72] | Ks[128][72] | Vs[128][72] | Ps[128][136] | ksq f32[128] | lsum f32[128][2]
#define SA_Q    0
#define SA_K    18432
#define SA_V    36864
#define SA_P    55296
#define SA_KSQ  90112
#define SA_LSUM 90624
#define SA_BYTES 91648

__global__ __launch_bounds__(256, 2) void attention_kernel(const float* __restrict__ tempPtr)
{
    extern __shared__ __align__(16) char smc[];
    float* ksq = (float*)(smc + SA_KSQ);
    float* lsum = (float*)(smc + SA_LSUM);
    const uint32_t sQ = smem_u32(smc + SA_Q);
    const uint32_t sK = smem_u32(smc + SA_K);
    const uint32_t sV = smem_u32(smc + SA_V);
    const uint32_t sP = smem_u32(smc + SA_P);

    const int tid = threadIdx.x, lane = tid & 31, warp = tid >> 5;
    const int g = lane >> 2, tg = lane & 3;
    const int mw = (warp >> 1) * 32;
    const int nhalf = warp & 1;
    const int nw = nhalf * 64;        // S col group (64 keys)
    const int nwo = nhalf * 32;       // O col group (32 hdim)

    // A-frag bases: Q rows 144 B, P rows 272 B
    const uint32_t aQb = sQ + (mw + (lane & 15)) * 144 + ((lane >> 4) << 4);
    const uint32_t aPb = sP + (mw + (lane & 15)) * 272 + ((lane >> 4) << 4);
    // K B-frag (non-trans, K stored [key][d]): rows = keys
    const uint32_t bKb = sK + (nw + (lane & 7) + ((lane >> 4) << 3)) * 144 + (((lane >> 3) & 1) << 4);
    // V B-frag via ldmatrix.trans (V stored [key][d]): rows = keys (k dim), cols = hdim (n dim)
    //   tile lanes: 0-7 k0-7/n0-7, 8-15 k8-15/n0-7, 16-23 k0-7/n8-15, 24-31 k8-15/n8-15
    const uint32_t bVb = sV + ((lane & 7) + (((lane >> 3) & 1) << 3)) * 144
                            + (nwo + ((lane >> 4) << 3)) * 2;

    const int z = blockIdx.y;
    const int b = z / HEADS, h = z % HEADS;
    const int q0 = blockIdx.x * 128;
    const float invT = 1.0f / (*tempPtr);

    // Q tile load (once): 128 rows x 64 halfs
#pragma unroll
    for (int it = 0; it < 4; it++) {
        int idx = tid + it * 256;
        int r = idx >> 3, c = idx & 7;
        cp_async16(sQ + r * 144 + c * 16,
                   &g_Qh[(size_t)(b * SEQ + q0 + r) * EMBED + h * HDIM + c * 8]);
    }
    CP_COMMIT();

    float qqv[4];
#pragma unroll
    for (int mi = 0; mi < 2; mi++) {
        qqv[mi * 2 + 0] = g_qsq[(size_t)z * SEQ + q0 + mw + mi * 16 + g];
        qqv[mi * 2 + 1] = g_qsq[(size_t)z * SEQ + q0 + mw + mi * 16 + g + 8];
    }

    float oacc[2][4][4];
#pragma unroll
    for (int mi = 0; mi < 2; mi++)
#pragma unroll
        for (int ni = 0; ni < 4; ni++)
#pragma unroll
            for (int c = 0; c < 4; c++) oacc[mi][ni][c] = 0.f;
    float rsum[4] = {0.f, 0.f, 0.f, 0.f};

    for (int kt = 0; kt < 16; kt++) {
        const int kk0 = kt * 128;
        __syncthreads();
        // K tile [128 keys][64 d], V tile [128 keys][64 d]
#pragma unroll
        for (int it = 0; it < 4; it++) {
            int idx = tid + it * 256;
            int r = idx >> 3, c = idx & 7;
            cp_async16(sK + r * 144 + c * 16,
                       &g_Kh[(size_t)(b * SEQ + kk0 + r) * EMBED + h * HDIM + c * 8]);
            cp_async16(sV + r * 144 + c * 16,
                       &g_Vh[(size_t)(b * SEQ + kk0 + r) * EMBED + h * HDIM + c * 8]);
        }
        CP_COMMIT();
        if (tid < 32) {
            float4 v = ((const float4*)&g_ksq[(size_t)z * SEQ + kk0])[tid];
            ((float4*)ksq)[tid] = v;
        }
        CP_WAIT0();
        __syncthreads();

        // ---- S = Q @ K^T (warp: 32x64), k=64 -> 4 k16 steps ----
        float sacc[2][8][4];
#pragma unroll
        for (int mi = 0; mi < 2; mi++)
#pragma unroll
            for (int nj = 0; nj < 8; nj++)
#pragma unroll
                for (int c = 0; c < 4; c++) sacc[mi][nj][c] = 0.f;
#pragma unroll
        for (int ks = 0; ks < 4; ks++) {
            const uint32_t kb = ks * 32;
            uint32_t af[2][4], bf[8][2];
            ldmx4(af[0], aQb + kb);
            ldmx4(af[1], aQb + 16 * 144 + kb);
#pragma unroll
            for (int j = 0; j < 4; j++) {
                uint32_t t[4];
                ldmx4(t, bKb + j * 16 * 144 + kb);
                bf[j * 2][0] = t[0]; bf[j * 2][1] = t[1];
                bf[j * 2 + 1][0] = t[2]; bf[j * 2 + 1][1] = t[3];
            }
#pragma unroll
            for (int mi = 0; mi < 2; mi++)
#pragma unroll
                for (int nj = 0; nj < 8; nj++)
                    mma_f16(sacc[mi][nj], af[mi], bf[nj]);
        }

        // ---- epilogue: p = exp(-max(qq+kk-2s,0)/T) -> Ps (fp16) ----
#pragma unroll
        for (int mi = 0; mi < 2; mi++) {
            const int rlo = mw + mi * 16 + g, rhi = rlo + 8;
            const float qlo = qqv[mi * 2], qhi = qqv[mi * 2 + 1];
#pragma unroll
            for (int nj = 0; nj < 8; nj++) {
                const int col = nw + nj * 8 + tg * 2;
                const float kc0 = ksq[col], kc1 = ksq[col + 1];
                float p00 = __expf(-fmaxf(qlo + kc0 - 2.f * sacc[mi][nj][0], 0.f) * invT);
                float p01 = __expf(-fmaxf(qlo + kc1 - 2.f * sacc[mi][nj][1], 0.f) * invT);
                float p10 = __expf(-fmaxf(qhi + kc0 - 2.f * sacc[mi][nj][2], 0.f) * invT);
                float p11 = __expf(-fmaxf(qhi + kc1 - 2.f * sacc[mi][nj][3], 0.f) * invT);
                rsum[mi * 2 + 0] += p00 + p01;
                rsum[mi * 2 + 1] += p10 + p11;
                *(__half2*)(smc + SA_P + rlo * 272 + col * 2) = __floats2half2_rn(p00, p01);
                *(__half2*)(smc + SA_P + rhi * 272 + col * 2) = __floats2half2_rn(p10, p11);
            }
        }
        __syncthreads();

        // ---- O += P @ V (warp: 32x32, k=128 -> 8 k16 steps), V via ldmatrix.trans ----
#pragma unroll
        for (int ks = 0; ks < 8; ks++) {
            uint32_t paf[2][4], vbf[4][2];
            ldmx4(paf[0], aPb + ks * 32);
            ldmx4(paf[1], aPb + 16 * 272 + ks * 32);
#pragma unroll
            for (int j = 0; j < 2; j++) {
                uint32_t t[4];
                ldmx4t(t, bVb + ks * 2304 + j * 32);   // k-step = 16 rows * 144 B; j = +16 hdim
                vbf[j * 2][0] = t[0]; vbf[j * 2][1] = t[1];
                vbf[j * 2 + 1][0] = t[2]; vbf[j * 2 + 1][1] = t[3];
            }
#pragma unroll
            for (int mi = 0; mi < 2; mi++)
#pragma unroll
                for (int ni = 0; ni < 4; ni++)
                    mma_f16(oacc[mi][ni], paf[mi], vbf[ni]);
        }
    }

#pragma unroll
    for (int i = 0; i < 4; i++) {
        rsum[i] += __shfl_xor_sync(0xffffffffu, rsum[i], 1);
        rsum[i] += __shfl_xor_sync(0xffffffffu, rsum[i], 2);
    }
    __syncthreads();
    if (tg == 0) {
#pragma unroll
        for (int mi = 0; mi < 2; mi++) {
            lsum[(mw + mi * 16 + g) * 2 + nhalf]     = rsum[mi * 2 + 0];
            lsum[(mw + mi * 16 + g + 8) * 2 + nhalf] = rsum[mi * 2 + 1];
        }
    }
    __syncthreads();

    float linv[4];
#pragma unroll
    for (int mi = 0; mi < 2; mi++) {
        int rlo = mw + mi * 16 + g, rhi = rlo + 8;
        linv[mi * 2 + 0] = 1.f / (lsum[rlo * 2] + lsum[rlo * 2 + 1]);
        linv[mi * 2 + 1] = 1.f / (lsum[rhi * 2] + lsum[rhi * 2 + 1]);
    }

#pragma unroll
    for (int mi = 0; mi < 2; mi++)
#pragma unroll
        for (int ni = 0; ni < 4; ni++) {
            int rlo = mw + mi * 16 + g, rhi = rlo + 8;
            int col = nwo + ni * 8 + tg * 2;
            *(__half2*)&g_Oh[(size_t)(b * SEQ + q0 + rlo) * EMBED + h * HDIM + col] =
                __floats2half2_rn(oacc[mi][ni][0] * linv[mi * 2], oacc[mi][ni][1] * linv[mi * 2]);
            *(__half2*)&g_Oh[(size_t)(b * SEQ + q0 + rhi) * EMBED + h * HDIM + col] =
                __floats2half2_rn(oacc[mi][ni][2] * linv[mi * 2 + 1], oacc[mi][ni][3] * linv[mi * 2 + 1]);
        }
}

// ======================= launcher =======================
extern "C" void kernel_launch(void* const* d_in, const int* in_sizes, int n_in,
                              void* d_out, int out_size)
{
    const float* query = (const float*)d_in[0];
    const float* wq = (const float*)d_in[1];
    const float* bq = (const float*)d_in[2];
    const float* wk = (const float*)d_in[3];
    const float* bk = (const float*)d_in[4];
    const float* wv = (const float*)d_in[5];
    const float* bv = (const float*)d_in[6];
    const float* wo = (const float*)d_in[7];
    const float* bo = (const float*)d_in[8];
    const float* temperature = (const float*)d_in[9];
    float* out = (float*)d_out;

    cudaFuncSetAttribute(attention_kernel,
                         cudaFuncAttributeMaxDynamicSharedMemorySize, SA_BYTES);
    cudaFuncSetAttribute(proj_h_kernel<true>,
                         cudaFuncAttributeMaxDynamicSharedMemorySize, PROJ_SMEM);
    cudaFuncSetAttribute(proj_h_kernel<false>,
                         cudaFuncAttributeMaxDynamicSharedMemorySize, PROJ_SMEM);

    __half *Ahp, *Qhp, *Khp, *Vhp, *Ohp, *Wthp;
    cudaGetSymbolAddress((void**)&Ahp, g_Ah);
    cudaGetSymbolAddress((void**)&Qhp, g_Qh);
    cudaGetSymbolAddress((void**)&Khp, g_Kh);
    cudaGetSymbolAddress((void**)&Vhp, g_Vh);
    cudaGetSymbolAddress((void**)&Ohp, g_Oh);
    cudaGetSymbolAddress((void**)&Wthp, g_Wth);
    const __half *W0 = Wthp, *W1 = Wthp + (size_t)EMBED * EMBED,
                 *W2 = Wthp + 2 * (size_t)EMBED * EMBED, *W3 = Wthp + 3 * (size_t)EMBED * EMBED;

    round_query_kernel<<<(MROWS * EMBED) / (256 * 8), 256>>>(query);

    dim3 gTW(EMBED / 32, EMBED / 32, 4);
    transpose_w_kernel<<<gTW, 256>>>(wq, wk, wv, wo);

    // fused QKV projection (+ fused Q/K row norms): grid (8 n, 32 m, 3 z)
    dim3 gQKV(EMBED / 128, MROWS / 128, 3);
    proj_h_kernel<true><<<gQKV, 256, PROJ_SMEM>>>(Ahp, W0, W1, W2, bq, bk, bv, Qhp, Khp, Vhp);

    dim3 gAtt(SEQ / 128, B_BATCH * HEADS);    // (16, 32)
    attention_kernel<<<gAtt, 256, SA_BYTES>>>(temperature);

    // output projection: fp32 output + bias
    dim3 gOut(EMBED / 128, MROWS / 128, 1);
    proj_h_kernel<false><<<gOut, 256, PROJ_SMEM>>>(Ohp, W3, W3, W3, bo, bo, bo, out, out, out);
}

// round 17
// speedup vs baseline: 1.4898x; 1.4898x over previous
#include <cuda_runtime.h>
#include <cuda_fp16.h>
#include <cstdint>

#define B_BATCH 2
#define SEQ 2048
#define EMBED 1024
#define HEADS 16
#define HDIM 64
#define MROWS (B_BATCH * SEQ)   // 4096

// ---------------- scratch (device globals: allocation-free) ----------------
__device__ __half g_Ah[(size_t)MROWS * EMBED];                  // fp16-rounded query
__device__ __half g_Qh[(size_t)MROWS * EMBED];
__device__ __half g_Kh[(size_t)MROWS * EMBED];
__device__ __half g_Vh[(size_t)MROWS * EMBED];
__device__ __half g_Oh[(size_t)MROWS * EMBED];
__device__ __half g_Wth[(size_t)4 * EMBED * EMBED];             // transposed weights (fp16)
__device__ __half g_Vth[(size_t)B_BATCH * HEADS * HDIM * SEQ];  // V transposed per head
__device__ float g_qsq[(size_t)B_BATCH * HEADS * SEQ];
__device__ float g_ksq[(size_t)B_BATCH * HEADS * SEQ];

// ======================= helpers =======================
__device__ __forceinline__ uint32_t smem_u32(const void* p) {
    uint32_t a;
    asm("{ .reg .u64 t; cvta.to.shared.u64 t, %1; cvt.u32.u64 %0, t; }" : "=r"(a) : "l"(p));
    return a;
}
__device__ __forceinline__ void cp_async16(uint32_t dst, const void* src) {
    asm volatile("cp.async.cg.shared.global [%0], [%1], 16;" :: "r"(dst), "l"(src));
}
#define CP_COMMIT() asm volatile("cp.async.commit_group;" ::: "memory")
#define CP_WAIT0()  asm volatile("cp.async.wait_group 0;" ::: "memory")
#define CP_WAIT1()  asm volatile("cp.async.wait_group 1;" ::: "memory")

// mma.sync m16n8k16 fp16: D(f32) += A(f16)*B(f16)
__device__ __forceinline__ void mma_f16(float* d, const uint32_t* a, const uint32_t* b) {
    asm volatile(
        "mma.sync.aligned.m16n8k16.row.col.f32.f16.f16.f32 "
        "{%0,%1,%2,%3}, {%4,%5,%6,%7}, {%8,%9}, {%0,%1,%2,%3};"
        : "+f"(d[0]), "+f"(d[1]), "+f"(d[2]), "+f"(d[3])
        : "r"(a[0]), "r"(a[1]), "r"(a[2]), "r"(a[3]), "r"(b[0]), "r"(b[1]));
}
__device__ __forceinline__ void ldmx4(uint32_t* r, uint32_t addr) {
    asm volatile("ldmatrix.sync.aligned.m8n8.x4.shared.b16 {%0,%1,%2,%3}, [%4];"
        : "=r"(r[0]), "=r"(r[1]), "=r"(r[2]), "=r"(r[3]) : "r"(addr));
}

// ======================= round query to fp16 =======================
__global__ __launch_bounds__(256) void round_query_kernel(const float* __restrict__ in)
{
    size_t i = ((size_t)blockIdx.x * 256 + threadIdx.x) * 8;
    float4 a = *(const float4*)&in[i];
    float4 b = *(const float4*)&in[i + 4];
    __half2 h[4];
    h[0] = __floats2half2_rn(a.x, a.y);
    h[1] = __floats2half2_rn(a.z, a.w);
    h[2] = __floats2half2_rn(b.x, b.y);
    h[3] = __floats2half2_rn(b.z, b.w);
    *(uint4*)&g_Ah[i] = *(uint4*)h;
}

// ======================= transpose weights (+fp16 round) =======================
__global__ __launch_bounds__(256) void transpose_w_kernel(
    const float* __restrict__ wq, const float* __restrict__ wk,
    const float* __restrict__ wv, const float* __restrict__ wo)
{
    __shared__ float t[32][33];
    const int z = blockIdx.z;
    const float* W = (z == 0) ? wq : (z == 1) ? wk : (z == 2) ? wv : wo;
    __half* Out = g_Wth + (size_t)z * EMBED * EMBED;
    const int k0 = blockIdx.x * 32, n0 = blockIdx.y * 32;
    const int tx = threadIdx.x & 31, ty = threadIdx.x >> 5;
#pragma unroll
    for (int i = 0; i < 4; i++)
        t[ty + i * 8][tx] = W[(size_t)(k0 + ty + i * 8) * EMBED + n0 + tx];
    __syncthreads();
#pragma unroll
    for (int i = 0; i < 4; i++)
        Out[(size_t)(n0 + ty + i * 8) * EMBED + k0 + tx] = __float2half_rn(t[tx][ty + i * 8]);
}

// ======================= transpose V per head (fp16) =======================
__global__ __launch_bounds__(256) void transpose_v_kernel()
{
    __shared__ __half t[32][34];
    const int b = blockIdx.z;
    const int e0 = blockIdx.x * 32, s0 = blockIdx.y * 32;
    const int tx = threadIdx.x & 31, ty = threadIdx.x >> 5;
#pragma unroll
    for (int i = 0; i < 4; i++)
        t[ty + i * 8][tx] = g_Vh[(size_t)(b * SEQ + s0 + ty + i * 8) * EMBED + e0 + tx];
    __syncthreads();
#pragma unroll
    for (int i = 0; i < 4; i++) {
        int e = e0 + ty + i * 8;
        int s = s0 + tx;
        g_Vth[(size_t)(b * HEADS + (e >> 6)) * HDIM * SEQ + (size_t)(e & 63) * SEQ + s] =
            t[tx][ty + i * 8];
    }
}

// ======================= fp16 mma projection GEMM (128x128, BK=64, 3-stage) =======
// 256 threads, 8 warps (64x32 each). Stage: A[128][72] + B[128][72] halfs = 36864 B.
// HOUT (QKV) launches z<2 also emit per-row head-norms into g_qsq/g_ksq.
#define PROJ_STAGE_B 36864
#define PROJ_SMEM    (3 * PROJ_STAGE_B)   // 110592 bytes

template <bool HOUT>
__global__ __launch_bounds__(256, 2) void proj_h_kernel(
    const __half* __restrict__ A,
    const __half* __restrict__ B0, const __half* __restrict__ B1, const __half* __restrict__ B2,
    const float* __restrict__ bias0, const float* __restrict__ bias1, const float* __restrict__ bias2,
    void* __restrict__ C0v, void* __restrict__ C1v, void* __restrict__ C2v)
{
    extern __shared__ __align__(16) char smb[];
    const int z = blockIdx.z;
    const __half* Bt = (z == 0) ? B0 : (z == 1) ? B1 : B2;
    const float* bias = (z == 0) ? bias0 : (z == 1) ? bias1 : bias2;
    void* Cv = (z == 0) ? C0v : (z == 1) ? C1v : C2v;

    const uint32_t sBase = smem_u32(smb);
    const int tid = threadIdx.x, lane = tid & 31, warp = tid >> 5;
    const int g = lane >> 2, tg = lane & 3;
    const int m0 = blockIdx.y * 128, n0 = blockIdx.x * 128;
    const int mw = (warp >> 2) * 64, nw = (warp & 3) * 32;

    const uint32_t aOff = (mw + (lane & 15)) * 144 + ((lane >> 4) << 4);
    const uint32_t bOff = 18432 +
        (nw + (lane & 7) + ((lane >> 4) << 3)) * 144 + (((lane >> 3) & 1) << 4);

    float acc[4][4][4];
#pragma unroll
    for (int mi = 0; mi < 4; mi++)
#pragma unroll
        for (int ni = 0; ni < 4; ni++)
#pragma unroll
            for (int c = 0; c < 4; c++) acc[mi][ni][c] = 0.f;

    auto issue = [&](int kc) {
        const uint32_t sb = sBase + (kc % 3) * PROJ_STAGE_B;
        const int k0 = kc * 64;
#pragma unroll
        for (int it = 0; it < 4; it++) {
            int idx = tid + it * 256;
            int r = idx >> 3, c = idx & 7;
            cp_async16(sb + r * 144 + c * 16, &A[(size_t)(m0 + r) * EMBED + k0 + c * 8]);
            cp_async16(sb + 18432 + r * 144 + c * 16, &Bt[(size_t)(n0 + r) * EMBED + k0 + c * 8]);
        }
        CP_COMMIT();
    };

    issue(0); issue(1);
    for (int kc = 0; kc < 16; kc++) {
        if (kc == 15) { CP_WAIT0(); } else { CP_WAIT1(); }
        __syncthreads();
        if (kc + 2 < 16) issue(kc + 2);
        const uint32_t sb = sBase + (kc % 3) * PROJ_STAGE_B;
#pragma unroll
        for (int ks = 0; ks < 4; ks++) {
            const uint32_t kb = ks * 32;
            uint32_t af[4][4], bf[4][2];
#pragma unroll
            for (int mi = 0; mi < 4; mi++)
                ldmx4(af[mi], sb + aOff + mi * 2304 + kb);
#pragma unroll
            for (int j = 0; j < 2; j++) {
                uint32_t t[4];
                ldmx4(t, sb + bOff + j * 2304 + kb);
                bf[j * 2][0] = t[0]; bf[j * 2][1] = t[1];
                bf[j * 2 + 1][0] = t[2]; bf[j * 2 + 1][1] = t[3];
            }
#pragma unroll
            for (int mi = 0; mi < 4; mi++)
#pragma unroll
                for (int ni = 0; ni < 4; ni++)
                    mma_f16(acc[mi][ni], af[mi], bf[ni]);
        }
        __syncthreads();
    }

    float rp[8];
#pragma unroll
    for (int i = 0; i < 8; i++) rp[i] = 0.f;

#pragma unroll
    for (int mi = 0; mi < 4; mi++)
#pragma unroll
        for (int ni = 0; ni < 4; ni++) {
            int row = m0 + mw + mi * 16 + g;
            int col = n0 + nw + ni * 8 + tg * 2;
            float b0 = bias[col], b1 = bias[col + 1];
            if (HOUT) {
                __half* C = (__half*)Cv;
                __half2 h0 = __floats2half2_rn(acc[mi][ni][0] + b0, acc[mi][ni][1] + b1);
                __half2 h1 = __floats2half2_rn(acc[mi][ni][2] + b0, acc[mi][ni][3] + b1);
                *(__half2*)&C[(size_t)row * EMBED + col] = h0;
                *(__half2*)&C[(size_t)(row + 8) * EMBED + col] = h1;
                if (z < 2) {
                    float2 f0 = __half22float2(h0);
                    float2 f1 = __half22float2(h1);
                    rp[mi * 2 + 0] += f0.x * f0.x + f0.y * f0.y;
                    rp[mi * 2 + 1] += f1.x * f1.x + f1.y * f1.y;
                }
            } else {
                float* C = (float*)Cv;
                float2 v0 = { acc[mi][ni][0] + b0, acc[mi][ni][1] + b1 };
                float2 v1 = { acc[mi][ni][2] + b0, acc[mi][ni][3] + b1 };
                *(float2*)&C[(size_t)row * EMBED + col] = v0;
                *(float2*)&C[(size_t)(row + 8) * EMBED + col] = v1;
            }
        }

    if (HOUT && z < 2) {
#pragma unroll
        for (int i = 0; i < 8; i++) {
            rp[i] += __shfl_xor_sync(0xffffffffu, rp[i], 1);
            rp[i] += __shfl_xor_sync(0xffffffffu, rp[i], 2);
        }
        float* nsum = (float*)smb;
        __syncthreads();
        if (tg == 0) {
#pragma unroll
            for (int mi = 0; mi < 4; mi++) {
                nsum[(mw + mi * 16 + g) * 4 + (warp & 3)]     = rp[mi * 2 + 0];
                nsum[(mw + mi * 16 + g + 8) * 4 + (warp & 3)] = rp[mi * 2 + 1];
            }
        }
        __syncthreads();
        if (tid < 128) {
            int grow = m0 + tid;
            int bb = grow >> 11, s = grow & (SEQ - 1);
            int head0 = n0 >> 6;
            float v0 = nsum[tid * 4 + 0] + nsum[tid * 4 + 1];
            float v1 = nsum[tid * 4 + 2] + nsum[tid * 4 + 3];
            float* dst = (z == 0) ? g_qsq : g_ksq;
            dst[(size_t)(bb * HEADS + head0) * SEQ + s]     = v0;
            dst[(size_t)(bb * HEADS + head0 + 1) * SEQ + s] = v1;
        }
    }
}

// ======================= fused attention (fp16 mma, R14 structure) =======================
// Per block: one (b,h), one 128-row q-tile; 16 k-tiles of 128. 256 threads, 8 warps.
// Smem (halfs): Qs[128][72] | Ks[128][72] | Vts[64][136] | Ps[128][136] | ksq f32[128] | lsum f32[128][2]
#define SA_Q    0
#define SA_K    18432
#define SA_VT   36864
#define SA_P    54272
#define SA_KSQ  89088
#define SA_LSUM 89600
#define SA_BYTES 90624

__global__ __launch_bounds__(256, 2) void attention_kernel(const float* __restrict__ tempPtr)
{
    extern __shared__ __align__(16) char smc[];
    float* ksq = (float*)(smc + SA_KSQ);
    float* lsum = (float*)(smc + SA_LSUM);
    const uint32_t sQ = smem_u32(smc + SA_Q);
    const uint32_t sK = smem_u32(smc + SA_K);
    const uint32_t sVT = smem_u32(smc + SA_VT);
    const uint32_t sP = smem_u32(smc + SA_P);

    const int tid = threadIdx.x, lane = tid & 31, warp = tid >> 5;
    const int g = lane >> 2, tg = lane & 3;
    const int mw = (warp >> 1) * 32;
    const int nhalf = warp & 1;
    const int nw = nhalf * 64;
    const int nwo = nhalf * 32;

    const uint32_t aQb = sQ + (mw + (lane & 15)) * 144 + ((lane >> 4) << 4);
    const uint32_t aPb = sP + (mw + (lane & 15)) * 272 + ((lane >> 4) << 4);
    const uint32_t bKb = sK + (nw + (lane & 7) + ((lane >> 4) << 3)) * 144 + (((lane >> 3) & 1) << 4);
    const uint32_t bVb = sVT + (nwo + (lane & 7) + ((lane >> 4) << 3)) * 272 + (((lane >> 3) & 1) << 4);

    const int z = blockIdx.y;
    const int b = z / HEADS, h = z % HEADS;
    const int q0 = blockIdx.x * 128;
    const float invT = 1.0f / (*tempPtr);
    const size_t vtoff = (size_t)z * HDIM * SEQ;

    // Q tile load (once): 128 rows x 64 halfs
#pragma unroll
    for (int it = 0; it < 4; it++) {
        int idx = tid + it * 256;
        int r = idx >> 3, c = idx & 7;
        cp_async16(sQ + r * 144 + c * 16,
                   &g_Qh[(size_t)(b * SEQ + q0 + r) * EMBED + h * HDIM + c * 8]);
    }
    CP_COMMIT();

    float qqv[4];
#pragma unroll
    for (int mi = 0; mi < 2; mi++) {
        qqv[mi * 2 + 0] = g_qsq[(size_t)z * SEQ + q0 + mw + mi * 16 + g];
        qqv[mi * 2 + 1] = g_qsq[(size_t)z * SEQ + q0 + mw + mi * 16 + g + 8];
    }

    float oacc[2][4][4];
#pragma unroll
    for (int mi = 0; mi < 2; mi++)
#pragma unroll
        for (int ni = 0; ni < 4; ni++)
#pragma unroll
            for (int c = 0; c < 4; c++) oacc[mi][ni][c] = 0.f;
    float rsum[4] = {0.f, 0.f, 0.f, 0.f};

    for (int kt = 0; kt < 16; kt++) {
        const int kk0 = kt * 128;
        __syncthreads();
        // K tile [128 keys][64 d], Vt tile [64 d][128 keys]
#pragma unroll
        for (int it = 0; it < 4; it++) {
            int idx = tid + it * 256;
            {
                int r = idx >> 3, c = idx & 7;
                cp_async16(sK + r * 144 + c * 16,
                           &g_Kh[(size_t)(b * SEQ + kk0 + r) * EMBED + h * HDIM + c * 8]);
            }
            {
                int r = idx >> 4, c = idx & 15;
                cp_async16(sVT + r * 272 + c * 16,
                           &g_Vth[vtoff + (size_t)r * SEQ + kk0 + c * 8]);
            }
        }
        CP_COMMIT();
        if (tid < 32) {
            float4 v = ((const float4*)&g_ksq[(size_t)z * SEQ + kk0])[tid];
            ((float4*)ksq)[tid] = v;
        }
        CP_WAIT0();
        __syncthreads();

        // ---- S = Q @ K^T (warp: 32x64), k=64 -> 4 k16 steps ----
        float sacc[2][8][4];
#pragma unroll
        for (int mi = 0; mi < 2; mi++)
#pragma unroll
            for (int nj = 0; nj < 8; nj++)
#pragma unroll
                for (int c = 0; c < 4; c++) sacc[mi][nj][c] = 0.f;
#pragma unroll
        for (int ks = 0; ks < 4; ks++) {
            const uint32_t kb = ks * 32;
            uint32_t af[2][4], bf[8][2];
            ldmx4(af[0], aQb + kb);
            ldmx4(af[1], aQb + 16 * 144 + kb);
#pragma unroll
            for (int j = 0; j < 4; j++) {
                uint32_t t[4];
                ldmx4(t, bKb + j * 16 * 144 + kb);
                bf[j * 2][0] = t[0]; bf[j * 2][1] = t[1];
                bf[j * 2 + 1][0] = t[2]; bf[j * 2 + 1][1] = t[3];
            }
#pragma unroll
            for (int mi = 0; mi < 2; mi++)
#pragma unroll
                for (int nj = 0; nj < 8; nj++)
                    mma_f16(sacc[mi][nj], af[mi], bf[nj]);
        }

        // ---- epilogue: p = exp(-max(qq+kk-2s,0)/T) -> Ps (fp16) ----
#pragma unroll
        for (int mi = 0; mi < 2; mi++) {
            const int rlo = mw + mi * 16 + g, rhi = rlo + 8;
            const float qlo = qqv[mi * 2], qhi = qqv[mi * 2 + 1];
#pragma unroll
            for (int nj = 0; nj < 8; nj++) {
                const int col = nw + nj * 8 + tg * 2;
                const float kc0 = ksq[col], kc1 = ksq[col + 1];
                float p00 = __expf(-fmaxf(qlo + kc0 - 2.f * sacc[mi][nj][0], 0.f) * invT);
                float p01 = __expf(-fmaxf(qlo + kc1 - 2.f * sacc[mi][nj][1], 0.f) * invT);
                float p10 = __expf(-fmaxf(qhi + kc0 - 2.f * sacc[mi][nj][2], 0.f) * invT);
                float p11 = __expf(-fmaxf(qhi + kc1 - 2.f * sacc[mi][nj][3], 0.f) * invT);
                rsum[mi * 2 + 0] += p00 + p01;
                rsum[mi * 2 + 1] += p10 + p11;
                *(__half2*)(smc + SA_P + rlo * 272 + col * 2) = __floats2half2_rn(p00, p01);
                *(__half2*)(smc + SA_P + rhi * 272 + col * 2) = __floats2half2_rn(p10, p11);
            }
        }
        __syncthreads();

        // ---- O += P @ V (warp: 32x32, k=128 -> 8 k16 steps) ----
#pragma unroll
        for (int ks = 0; ks < 8; ks++) {
            const uint32_t kb = ks * 32;
            uint32_t paf[2][4], vbf[4][2];
            ldmx4(paf[0], aPb + kb);
            ldmx4(paf[1], aPb + 16 * 272 + kb);
#pragma unroll
            for (int j = 0; j < 2; j++) {
                uint32_t t[4];
                ldmx4(t, bVb + j * 16 * 272 + kb);
                vbf[j * 2][0] = t[0]; vbf[j * 2][1] = t[1];
                vbf[j * 2 + 1][0] = t[2]; vbf[j * 2 + 1][1] = t[3];
            }
#pragma unroll
            for (int mi = 0; mi < 2; mi++)
#pragma unroll
                for (int ni = 0; ni < 4; ni++)
                    mma_f16(oacc[mi][ni], paf[mi], vbf[ni]);
        }
    }

#pragma unroll
    for (int i = 0; i < 4; i++) {
        rsum[i] += __shfl_xor_sync(0xffffffffu, rsum[i], 1);
        rsum[i] += __shfl_xor_sync(0xffffffffu, rsum[i], 2);
    }
    __syncthreads();
    if (tg == 0) {
#pragma unroll
        for (int mi = 0; mi < 2; mi++) {
            lsum[(mw + mi * 16 + g) * 2 + nhalf]     = rsum[mi * 2 + 0];
            lsum[(mw + mi * 16 + g + 8) * 2 + nhalf] = rsum[mi * 2 + 1];
        }
    }
    __syncthreads();

    float linv[4];
#pragma unroll
    for (int mi = 0; mi < 2; mi++) {
        int rlo = mw + mi * 16 + g, rhi = rlo + 8;
        linv[mi * 2 + 0] = 1.f / (lsum[rlo * 2] + lsum[rlo * 2 + 1]);
        linv[mi * 2 + 1] = 1.f / (lsum[rhi * 2] + lsum[rhi * 2 + 1]);
    }

#pragma unroll
    for (int mi = 0; mi < 2; mi++)
#pragma unroll
        for (int ni = 0; ni < 4; ni++) {
            int rlo = mw + mi * 16 + g, rhi = rlo + 8;
            int col = nwo + ni * 8 + tg * 2;
            *(__half2*)&g_Oh[(size_t)(b * SEQ + q0 + rlo) * EMBED + h * HDIM + col] =
                __floats2half2_rn(oacc[mi][ni][0] * linv[mi * 2], oacc[mi][ni][1] * linv[mi * 2]);
            *(__half2*)&g_Oh[(size_t)(b * SEQ + q0 + rhi) * EMBED + h * HDIM + col] =
                __floats2half2_rn(oacc[mi][ni][2] * linv[mi * 2 + 1], oacc[mi][ni][3] * linv[mi * 2 + 1]);
        }
}

// ======================= launcher =======================
extern "C" void kernel_launch(void* const* d_in, const int* in_sizes, int n_in,
                              void* d_out, int out_size)
{
    const float* query = (const float*)d_in[0];
    const float* wq = (const float*)d_in[1];
    const float* bq = (const float*)d_in[2];
    const float* wk = (const float*)d_in[3];
    const float* bk = (const float*)d_in[4];
    const float* wv = (const float*)d_in[5];
    const float* bv = (const float*)d_in[6];
    const float* wo = (const float*)d_in[7];
    const float* bo = (const float*)d_in[8];
    const float* temperature = (const float*)d_in[9];
    float* out = (float*)d_out;

    cudaFuncSetAttribute(attention_kernel,
                         cudaFuncAttributeMaxDynamicSharedMemorySize, SA_BYTES);
    cudaFuncSetAttribute(proj_h_kernel<true>,
                         cudaFuncAttributeMaxDynamicSharedMemorySize, PROJ_SMEM);
    cudaFuncSetAttribute(proj_h_kernel<false>,
                         cudaFuncAttributeMaxDynamicSharedMemorySize, PROJ_SMEM);

    __half *Ahp, *Qhp, *Khp, *Vhp, *Ohp, *Wthp;
    cudaGetSymbolAddress((void**)&Ahp, g_Ah);
    cudaGetSymbolAddress((void**)&Qhp, g_Qh);
    cudaGetSymbolAddress((void**)&Khp, g_Kh);
    cudaGetSymbolAddress((void**)&Vhp, g_Vh);
    cudaGetSymbolAddress((void**)&Ohp, g_Oh);
    cudaGetSymbolAddress((void**)&Wthp, g_Wth);
    const __half *W0 = Wthp, *W1 = Wthp + (size_t)EMBED * EMBED,
                 *W2 = Wthp + 2 * (size_t)EMBED * EMBED, *W3 = Wthp + 3 * (size_t)EMBED * EMBED;

    round_query_kernel<<<(MROWS * EMBED) / (256 * 8), 256>>>(query);

    dim3 gTW(EMBED / 32, EMBED / 32, 4);
    transpose_w_kernel<<<gTW, 256>>>(wq, wk, wv, wo);

    // fused QKV projection (+ fused Q/K row norms): grid (8 n, 32 m, 3 z)
    dim3 gQKV(EMBED / 128, MROWS / 128, 3);
    proj_h_kernel<true><<<gQKV, 256, PROJ_SMEM>>>(Ahp, W0, W1, W2, bq, bk, bv, Qhp, Khp, Vhp);

    dim3 gTV(EMBED / 32, SEQ / 32, B_BATCH);
    transpose_v_kernel<<<gTV, 256>>>();

    dim3 gAtt(SEQ / 128, B_BATCH * HEADS);    // (16, 32)
    attention_kernel<<<gAtt, 256, SA_BYTES>>>(temperature);

    // output projection: fp32 output + bias
    dim3 gOut(EMBED / 128, MROWS / 128, 1);
    proj_h_kernel<false><<<gOut, 256, PROJ_SMEM>>>(Ohp, W3, W3, W3, bo, bo, bo, out, out, out);
}